// round 4
// baseline (speedup 1.0000x reference)
#include <cuda_runtime.h>
#include <cstdint>
#include <cstddef>

// ---------------------------------------------------------------------------
// PointSampler: jax threefry masked random-permutation sampling.
//   x [B,C,H,W] f32, mask [B,1,H,W] f32, k=4096
//   out = concat( samples[B,k,C], b_idx[B,k], h_idx[B,k], w_idx[B,k] ) f32
// Pipeline: sel_a (hist, 128 CTAs) -> sel_b (scan, 16) -> sel_c (scatter, 128)
//           -> sel_d (rank+compact+idx, 16) -> gather (1024 CTAs)
// ---------------------------------------------------------------------------

constexpr int B = 16, C = 256, H = 128, W = 128;
constexpr int L = H * W;        // 16384
constexpr int K = 4096;
constexpr int NBIN = 16385;     // 16384 key bins + 1 unmasked sentinel
constexpr int Q = 8;            // histogram split per batch
constexpr int QELEM = L / Q;    // 2048

constexpr int WIN = K + 128;    // slot window ranked in sel_d

constexpr int CT = 4;           // gather channel tile
constexpr int STG = 4104;       // stage stride: 4104 % 32 == 8 -> conflict-free

constexpr int SMEM_A = NBIN * 4;
constexpr int SMEM_B = NBIN * 4 + 1024 * 4;
constexpr int SMEM_D = WIN * 8 + L * 2 + K * 4 + 1024 * 4;
constexpr int SMEM_G = K * 4 + CT * STG * 4;

__device__ uint32_t g_hist[B * Q * NBIN];
__device__ uint32_t g_base[B * NBIN];
__device__ uint64_t g_sorted[B * L];
__device__ uint32_t g_pos[B * K];      // rank -> flat position
__device__ uint32_t g_sel[B * K];      // pos-sorted: (pos<<16) | rank
__device__ int      g_counts[B];

// ---- jax threefry2x32 (20 rounds), partitionable mode ---------------------
__device__ __forceinline__ uint32_t jax_bits(uint32_t n) {
    uint32_t k0 = 0u, k1 = 42u;
    uint32_t ks2 = k0 ^ k1 ^ 0x1BD11BDAu;
    uint32_t x0 = k0, x1 = n + k1;
#define TF_RND(r) { x0 += x1; x1 = __funnelshift_l(x1, x1, (r)); x1 ^= x0; }
    TF_RND(13) TF_RND(15) TF_RND(26) TF_RND(6)
    x0 += k1;  x1 += ks2 + 1u;
    TF_RND(17) TF_RND(29) TF_RND(16) TF_RND(24)
    x0 += ks2; x1 += k0 + 2u;
    TF_RND(13) TF_RND(15) TF_RND(26) TF_RND(6)
    x0 += k0;  x1 += k1 + 3u;
    TF_RND(17) TF_RND(29) TF_RND(16) TF_RND(24)
    x0 += k1;  x1 += ks2 + 4u;
    TF_RND(13) TF_RND(15) TF_RND(26) TF_RND(6)
    x0 += ks2; x1 += k0 + 5u;
#undef TF_RND
    return x0 ^ x1;
}

__device__ __forceinline__ uint64_t make_key(uint32_t n, const float* mask,
                                             uint32_t& bin) {
    uint32_t bits = jax_bits(n);
    bool masked = mask[n] > 0.5f;
    uint32_t mkey = masked ? (bits >> 9) : 0x800000u;
    bin = mkey >> 9;                              // 0..16384
    uint32_t l = n & (uint32_t)(L - 1);
    return (((uint64_t)mkey) << 14) | (uint64_t)l;
}

// ---- sel_a: per-chunk histograms (no contention, fresh every replay) ------
__global__ __launch_bounds__(1024) void sel_a(const float* __restrict__ mask) {
    extern __shared__ uint32_t hist[];            // NBIN
    const int b = blockIdx.x >> 3;
    const int q = blockIdx.x & 7;
    const int t = threadIdx.x;
    for (int i = t; i < NBIN; i += 1024) hist[i] = 0u;
    __syncthreads();
#pragma unroll
    for (int i = 0; i < QELEM / 1024; i++) {
        uint32_t n = (uint32_t)(b * L + q * QELEM + t + i * 1024);
        uint32_t bin;
        make_key(n, mask, bin);
        atomicAdd(&hist[bin], 1u);
    }
    __syncthreads();
    uint32_t* gh = g_hist + (size_t)blockIdx.x * NBIN;
    for (int i = t; i < NBIN; i += 1024) gh[i] = hist[i];
}

// ---- sel_b: merge + exclusive scan -> g_base, g_counts --------------------
__global__ __launch_bounds__(1024) void sel_b() {
    extern __shared__ uint32_t sm_b[];
    uint32_t* tot = sm_b;                         // NBIN
    uint32_t* part = sm_b + NBIN;                 // 1024
    const int b = blockIdx.x;
    const int t = threadIdx.x;
    for (int i = t; i < NBIN; i += 1024) {
        uint32_t s = 0;
#pragma unroll
        for (int q = 0; q < Q; q++)
            s += g_hist[((size_t)(b * Q + q)) * NBIN + i];
        tot[i] = s;
    }
    __syncthreads();
    const int start = t * 16;
    const int cnt = (t == 1023) ? 17 : 16;
    uint32_t s = 0;
    for (int i = 0; i < cnt; i++) s += tot[start + i];
    part[t] = s;
    __syncthreads();
    for (int off = 1; off < 1024; off <<= 1) {
        uint32_t v = part[t];
        uint32_t a = (t >= off) ? part[t - off] : 0u;
        __syncthreads();
        part[t] = v + a;
        __syncthreads();
    }
    uint32_t run = (t == 0) ? 0u : part[t - 1];
    for (int i = 0; i < cnt; i++) {
        uint32_t h = tot[start + i];
        tot[start + i] = run;
        run += h;
    }
    __syncthreads();
    for (int i = t; i < NBIN; i += 1024) g_base[b * NBIN + i] = tot[i];
    if (t == 0) g_counts[b] = (int)tot[16384];
}

// ---- sel_c: global-atomic scatter of masked keys into bin slots -----------
__global__ __launch_bounds__(1024) void sel_c(const float* __restrict__ mask) {
    const int b = blockIdx.x >> 3;
    const int q = blockIdx.x & 7;
    const int t = threadIdx.x;
#pragma unroll
    for (int i = 0; i < QELEM / 1024; i++) {
        uint32_t n = (uint32_t)(b * L + q * QELEM + t + i * 1024);
        uint32_t bin;
        uint64_t kv = make_key(n, mask, bin);
        if (bin < 16384u) {                        // masked only
            uint32_t slot = atomicAdd(&g_base[b * NBIN + bin], 1u);
            g_sorted[(size_t)b * L + slot] = kv;
        }
    }
}

// ---- sel_d: rank first K+eps slots, pos->rank map, compact, idx out -------
__global__ __launch_bounds__(1024, 1) void sel_d(float* __restrict__ out,
                                                 int out_size) {
    extern __shared__ unsigned char sm[];
    uint64_t* pairs  = (uint64_t*)sm;                             // WIN
    uint16_t* slotm  = (uint16_t*)(sm + (size_t)WIN * 8);         // L
    uint32_t* rankpos = (uint32_t*)(sm + (size_t)WIN * 8 + L * 2); // K
    uint32_t* part   = (uint32_t*)(sm + (size_t)WIN * 8 + L * 2 + K * 4);

    const int b = blockIdx.x;
    const int t = threadIdx.x;
    const int count = g_counts[b];
    const int nwin  = (count < WIN) ? count : WIN;
    const int nproc = (count < K + 96) ? count : (K + 96);

    for (int i = t; i < nwin; i += 1024)
        pairs[i] = g_sorted[(size_t)b * L + i];
    {
        uint32_t* ss = (uint32_t*)slotm;
        for (int i = t; i < L / 2; i += 1024) ss[i] = 0xFFFFFFFFu;
    }
    __syncthreads();

    for (int sI = t; sI < nproc; sI += 1024) {
        uint64_t kv = pairs[sI];
        uint32_t bn = (uint32_t)(kv >> 23);
        int g = sI;
        while (g > 0 && (uint32_t)(pairs[g - 1] >> 23) == bn) g--;
        int r = 0;
        for (int u = g; u < nwin; u++) {
            uint64_t pk = pairs[u];
            if ((uint32_t)(pk >> 23) != bn) break;
            if (pk < kv) r++;
        }
        int rank = g + r;
        if (rank < K) {
            uint32_t p = (uint32_t)(kv & (uint64_t)(L - 1));
            g_pos[b * K + rank] = p;
            rankpos[rank] = p;
            slotm[p] = (uint16_t)rank;
        }
    }
    __syncthreads();

    // compact pos-sorted (pos<<16)|rank list
    {
        const int p0 = t * 16;
        uint32_t c2 = 0;
#pragma unroll
        for (int i = 0; i < 16; i++)
            if (slotm[p0 + i] != 0xFFFFu) c2++;
        part[t] = c2;
        __syncthreads();
        for (int off = 1; off < 1024; off <<= 1) {
            uint32_t v = part[t];
            uint32_t a = (t >= off) ? part[t - off] : 0u;
            __syncthreads();
            part[t] = v + a;
            __syncthreads();
        }
        uint32_t base = part[t] - c2;
#pragma unroll
        for (int i = 0; i < 16; i++) {
            uint16_t rk = slotm[p0 + i];
            if (rk != 0xFFFFu)
                g_sel[b * K + (base++)] = ((uint32_t)(p0 + i) << 16) | (uint32_t)rk;
        }
    }

    // (b, h, w) index outputs
    size_t off = (size_t)B * K * C;
    if ((size_t)out_size >= off + 3u * (size_t)(B * K)) {
        for (int j = t; j < K; j += 1024) {
            int eff = (j < count) ? j : (j % count);
            uint32_t p = rankpos[eff];
            size_t i = (size_t)b * K + j;
            out[off + i] = (float)b;
            out[off + (size_t)(B * K) + i] = (float)(p >> 7);
            out[off + 2u * (size_t)(B * K) + i] = (float)(p & (W - 1));
        }
    }
}

// ---- gather: compact-list, 2 CTAs/SM --------------------------------------
__global__ __launch_bounds__(1024, 2) void gather_kernel(
        const float* __restrict__ x, float* __restrict__ out) {
    extern __shared__ unsigned char sm[];
    uint32_t* sel = (uint32_t*)sm;                         // K
    float* stage = (float*)(sm + (size_t)K * 4);           // [CT][STG]

    const int b = blockIdx.y;
    const int c0 = blockIdx.x * CT;
    const int t = threadIdx.x;
    const int cb = g_counts[b];
    const int nsel = (cb < K) ? cb : K;
    if (nsel <= 0) return;

    for (int i = t; i < K; i += 1024)
        sel[i] = g_sel[b * K + i];
    __syncthreads();

    // 256 threads per plane, 16 loads each (8-deep batches)
    const int ci = t >> 8;          // 0..3
    const int ii = t & 255;
    const float* plane = x + ((size_t)(b * C + c0 + ci)) * (size_t)L;
    float* st = stage + (size_t)ci * STG;

#pragma unroll
    for (int s0 = 0; s0 < 16; s0 += 8) {
        uint32_t e[8];
        float v[8];
#pragma unroll
        for (int u = 0; u < 8; u++) {
            int idx = ii + (s0 + u) * 256;
            int cl = (idx < nsel) ? idx : (nsel - 1);  // clamp: benign dup store
            e[u] = sel[cl];
        }
#pragma unroll
        for (int u = 0; u < 8; u++) v[u] = __ldg(&plane[e[u] >> 16]);
#pragma unroll
        for (int u = 0; u < 8; u++) st[e[u] & 0xFFFFu] = v[u];
    }
    __syncthreads();

    // write-out: warp = 8 ranks x 4 channels (16B contiguous per rank)
    const int c = t & 3;
    const int jl = t >> 2;          // 0..255
#pragma unroll
    for (int r = 0; r < 16; r++) {
        int j = jl + r * 256;
        if (j < nsel)
            out[((size_t)b * K + j) * (size_t)C + c0 + c] = stage[(size_t)c * STG + j];
    }

    // wrap fallback (count < K) — no-op in practice
    for (int j = cb + t; j < K; j += 1024) {
        uint32_t p = g_pos[b * K + (j % cb)];
#pragma unroll
        for (int cc = 0; cc < CT; cc++)
            out[((size_t)b * K + j) * (size_t)C + c0 + cc] =
                __ldg(&x[((size_t)(b * C + c0 + cc)) * (size_t)L + p]);
    }
}

extern "C" void kernel_launch(void* const* d_in, const int* in_sizes, int n_in,
                              void* d_out, int out_size) {
    const float* x = (const float*)d_in[0];
    int mi = n_in - 1;
    for (int i = 1; i < n_in; i++)
        if (in_sizes[i] == B * L) { mi = i; break; }
    const float* mask = (const float*)d_in[mi];
    float* out = (float*)d_out;

    static bool attr_done = false;
    if (!attr_done) {
        cudaFuncSetAttribute(sel_a, cudaFuncAttributeMaxDynamicSharedMemorySize, SMEM_A);
        cudaFuncSetAttribute(sel_b, cudaFuncAttributeMaxDynamicSharedMemorySize, SMEM_B);
        cudaFuncSetAttribute(sel_d, cudaFuncAttributeMaxDynamicSharedMemorySize, SMEM_D);
        cudaFuncSetAttribute(gather_kernel, cudaFuncAttributeMaxDynamicSharedMemorySize, SMEM_G);
        attr_done = true;
    }

    sel_a<<<B * Q, 1024, SMEM_A>>>(mask);
    sel_b<<<B, 1024, SMEM_B>>>();
    sel_c<<<B * Q, 1024>>>(mask);
    sel_d<<<B, 1024, SMEM_D>>>(out, out_size);
    dim3 gg(C / CT, B);
    gather_kernel<<<gg, 1024, SMEM_G>>>(x, out);
}